// round 1
// baseline (speedup 1.0000x reference)
#include <cuda_runtime.h>

// Problem constants (fixed shapes from reference)
#define BATCH   2
#define SEQ     2048
#define DMODEL  1024
#define NHEADS  16
#define HDIM    64
#define NOUT    3072                 // 3 * DMODEL
#define M_GEMM  (BATCH * SEQ)        // 4096
#define K_GEMM  DMODEL               // 1024

// Scratch: Q/K/V in [b][h][s][hd] layout (16 MB each)
__device__ float g_Q[BATCH * NHEADS * SEQ * HDIM];
__device__ float g_K[BATCH * NHEADS * SEQ * HDIM];
__device__ float g_V[BATCH * NHEADS * SEQ * HDIM];

// ---------------------------------------------------------------------------
// Kernel 1: QKV projection.  C[m][n] = sum_k x[m][k] * w[n][k] + bias[n]
// 128x128 tile, BK=8, 256 threads, 8x8 per-thread microtile.
// Epilogue scatters into g_Q / g_K / g_V ([b][h][s][64]).
// ---------------------------------------------------------------------------
__global__ __launch_bounds__(256) void qkv_gemm_kernel(
    const float* __restrict__ A,      // [4096, 1024]
    const float* __restrict__ W,      // [3072, 1024]
    const float* __restrict__ bias)   // [3072]
{
    __shared__ float As[8][128];
    __shared__ float Bs[8][128];

    const int tid  = threadIdx.x;
    const int row0 = blockIdx.y * 128;   // m tile
    const int col0 = blockIdx.x * 128;   // n tile

    // loader coords: each thread loads one float4 of A and one of W per k-step
    const int ldr = tid >> 1;            // 0..127
    const int ldc = (tid & 1) * 4;       // 0 or 4

    // compute coords
    const int tr = (tid >> 4) << 3;      // 0..120 step 8
    const int tc = (tid & 15) << 3;      // 0..120 step 8

    float acc[8][8];
#pragma unroll
    for (int i = 0; i < 8; i++)
#pragma unroll
        for (int j = 0; j < 8; j++) acc[i][j] = 0.f;

    const float* Aptr = A + (size_t)(row0 + ldr) * K_GEMM + ldc;
    const float* Wptr = W + (size_t)(col0 + ldr) * K_GEMM + ldc;

    for (int k0 = 0; k0 < K_GEMM; k0 += 8) {
        float4 av = *(const float4*)(Aptr + k0);
        float4 wv = *(const float4*)(Wptr + k0);
        As[ldc + 0][ldr] = av.x;
        As[ldc + 1][ldr] = av.y;
        As[ldc + 2][ldr] = av.z;
        As[ldc + 3][ldr] = av.w;
        Bs[ldc + 0][ldr] = wv.x;
        Bs[ldc + 1][ldr] = wv.y;
        Bs[ldc + 2][ldr] = wv.z;
        Bs[ldc + 3][ldr] = wv.w;
        __syncthreads();

#pragma unroll
        for (int k = 0; k < 8; k++) {
            float4 a0 = *(const float4*)&As[k][tr];
            float4 a1 = *(const float4*)&As[k][tr + 4];
            float4 b0 = *(const float4*)&Bs[k][tc];
            float4 b1 = *(const float4*)&Bs[k][tc + 4];
            float ar[8] = {a0.x, a0.y, a0.z, a0.w, a1.x, a1.y, a1.z, a1.w};
            float br[8] = {b0.x, b0.y, b0.z, b0.w, b1.x, b1.y, b1.z, b1.w};
#pragma unroll
            for (int i = 0; i < 8; i++)
#pragma unroll
                for (int j = 0; j < 8; j++) acc[i][j] += ar[i] * br[j];
        }
        __syncthreads();
    }

    // epilogue: bias + scatter into Q/K/V ([b][h][s][64])
#pragma unroll
    for (int j = 0; j < 8; j++) {
        const int n = col0 + tc + j;
        const int h = n / 192;
        const int r = n - h * 192;
        const int which = r >> 6;        // 0=Q,1=K,2=V
        const int d = r & 63;
        float* dst = (which == 0) ? g_Q : ((which == 1) ? g_K : g_V);
        const float bv = bias[n];
#pragma unroll
        for (int i = 0; i < 8; i++) {
            const int m = row0 + tr + i;
            const int b = m >> 11;       // / 2048
            const int s = m & 2047;
            dst[(((size_t)(b * NHEADS + h) * SEQ) + s) * HDIM + d] = acc[i][j] + bv;
        }
    }
}

// ---------------------------------------------------------------------------
// Kernel 2: flash attention, fp32.
// One thread per query row: q[64] and o[64] live in registers.
// K/V tiles of 64 keys staged in shared. Online softmax; the o-rescale only
// fires when the running max changes (rare after warmup).
// Output written directly to d_out in [b][h][s][64] order (== reference
// reshape of the contiguous [b,h,s,hd] values tensor).
// ---------------------------------------------------------------------------
__global__ __launch_bounds__(128) void attn_kernel(float* __restrict__ out)
{
    const int bh = blockIdx.y;                 // 0..31
    const int q  = blockIdx.x * 128 + threadIdx.x;
    const int t  = threadIdx.x;

    const float* qrow = g_Q + ((size_t)bh * SEQ + q) * HDIM;

    float4 q4[16], o4[16];
#pragma unroll
    for (int i = 0; i < 16; i++) {
        q4[i] = ((const float4*)qrow)[i];
        o4[i] = make_float4(0.f, 0.f, 0.f, 0.f);
    }
    float m = -1e30f, l = 0.f;

    __shared__ float4 Ks[64][16];
    __shared__ float4 Vs[64][16];

    const float4* Kg = (const float4*)(g_K + (size_t)bh * SEQ * HDIM);
    const float4* Vg = (const float4*)(g_V + (size_t)bh * SEQ * HDIM);

    for (int j0 = 0; j0 < SEQ; j0 += 64) {
        __syncthreads();
        // stage 64 keys + 64 values: 1024 float4 each, 8 per thread
#pragma unroll
        for (int i = 0; i < 8; i++) {
            const int idx = t + i * 128;      // 0..1023
            const int row = idx >> 4;
            const int col = idx & 15;
            Ks[row][col] = Kg[(size_t)j0 * 16 + idx];
            Vs[row][col] = Vg[(size_t)j0 * 16 + idx];
        }
        __syncthreads();

#pragma unroll 2
        for (int j = 0; j < 64; j++) {
            float s0 = 0.f, s1 = 0.f, s2 = 0.f, s3 = 0.f;
#pragma unroll
            for (int d = 0; d < 16; d += 4) {
                float4 k0 = Ks[j][d + 0];
                float4 k1 = Ks[j][d + 1];
                float4 k2 = Ks[j][d + 2];
                float4 k3 = Ks[j][d + 3];
                s0 += q4[d + 0].x * k0.x + q4[d + 0].y * k0.y + q4[d + 0].z * k0.z + q4[d + 0].w * k0.w;
                s1 += q4[d + 1].x * k1.x + q4[d + 1].y * k1.y + q4[d + 1].z * k1.z + q4[d + 1].w * k1.w;
                s2 += q4[d + 2].x * k2.x + q4[d + 2].y * k2.y + q4[d + 2].z * k2.z + q4[d + 2].w * k2.w;
                s3 += q4[d + 3].x * k3.x + q4[d + 3].y * k3.y + q4[d + 3].z * k3.z + q4[d + 3].w * k3.w;
            }
            const float s = ((s0 + s1) + (s2 + s3)) * 0.125f;   // 1/sqrt(64)

            float p;
            if (s > m) {
                const float corr = __expf(m - s);
                l *= corr;
#pragma unroll
                for (int i = 0; i < 16; i++) {
                    o4[i].x *= corr; o4[i].y *= corr; o4[i].z *= corr; o4[i].w *= corr;
                }
                m = s;
                p = 1.f;
            } else {
                p = __expf(s - m);
            }
            l += p;

#pragma unroll
            for (int i = 0; i < 16; i++) {
                const float4 vv = Vs[j][i];
                o4[i].x += p * vv.x; o4[i].y += p * vv.y;
                o4[i].z += p * vv.z; o4[i].w += p * vv.w;
            }
        }
    }

    const float inv = 1.f / l;
    float4* orow = (float4*)(out + ((size_t)bh * SEQ + q) * HDIM);
#pragma unroll
    for (int i = 0; i < 16; i++) {
        float4 v = o4[i];
        v.x *= inv; v.y *= inv; v.z *= inv; v.w *= inv;
        orow[i] = v;
    }
}

// ---------------------------------------------------------------------------
extern "C" void kernel_launch(void* const* d_in, const int* in_sizes, int n_in,
                              void* d_out, int out_size)
{
    const float* x = (const float*)d_in[0];   // [2, 2048, 1024]
    const float* w = (const float*)d_in[1];   // [3072, 1024]
    const float* b = (const float*)d_in[2];   // [3072]
    float* out = (float*)d_out;               // [2, 2048, 1024] (head-interleaved)

    dim3 ggrid(NOUT / 128, M_GEMM / 128);     // (24, 32)
    qkv_gemm_kernel<<<ggrid, 256>>>(x, w, b);

    dim3 agrid(SEQ / 128, BATCH * NHEADS);    // (16, 32)
    attn_kernel<<<agrid, 128>>>(out);
}

// round 2
// speedup vs baseline: 3.2765x; 3.2765x over previous
#include <cuda_runtime.h>
#include <cstdint>

// Problem constants (fixed shapes from reference)
#define BATCH   2
#define SEQ     2048
#define DMODEL  1024
#define NHEADS  16
#define HDIM    64
#define NOUT    3072                 // 3 * DMODEL
#define M_GEMM  (BATCH * SEQ)        // 4096
#define K_GEMM  DMODEL               // 1024

// Scratch: Q/K/V in [b][h][s][hd] layout
__device__ float g_Q[BATCH * NHEADS * SEQ * HDIM];
__device__ float g_K[BATCH * NHEADS * SEQ * HDIM];
__device__ float g_V[BATCH * NHEADS * SEQ * HDIM];

// --------------------------- helpers ---------------------------------------
__device__ __forceinline__ uint32_t f2tf(float x) {
    uint32_t r;
    asm("cvt.rna.tf32.f32 %0, %1;" : "=r"(r) : "f"(x));
    return r;
}

__device__ __forceinline__ void mma_tf32(
    float& c0, float& c1, float& c2, float& c3,
    uint32_t a0, uint32_t a1, uint32_t a2, uint32_t a3,
    uint32_t b0, uint32_t b1)
{
    asm volatile(
        "mma.sync.aligned.m16n8k8.row.col.f32.tf32.tf32.f32 "
        "{%0,%1,%2,%3}, {%4,%5,%6,%7}, {%8,%9}, {%0,%1,%2,%3};"
        : "+f"(c0), "+f"(c1), "+f"(c2), "+f"(c3)
        : "r"(a0), "r"(a1), "r"(a2), "r"(a3), "r"(b0), "r"(b1));
}

// ---------------------------------------------------------------------------
// Kernel 1: QKV projection (tf32 tensor cores).
// C[m][n] = sum_k x[m][k] * w[n][k] + bias[n]
// Block tile 128x128, BK=32, 8 warps in 4(M) x 2(N); warp tile 32x64.
// Epilogue scatters into g_Q / g_K / g_V ([b][h][s][64]).
// ---------------------------------------------------------------------------
#define ASTR 36   // smem row stride (floats): (4g+c)%32 distinct -> conflict-free frags

__global__ __launch_bounds__(256) void qkv_gemm_kernel(
    const float* __restrict__ A,      // [4096, 1024]
    const float* __restrict__ W,      // [3072, 1024]
    const float* __restrict__ bias)   // [3072]
{
    __shared__ uint32_t As[128 * ASTR];
    __shared__ uint32_t Ws[128 * ASTR];

    const int tid  = threadIdx.x;
    const int w    = tid >> 5;
    const int lane = tid & 31;
    const int g    = lane >> 2;      // group id (0..7)
    const int c    = lane & 3;       // thread-in-group (0..3)
    const int warpM = w & 3;         // 0..3
    const int warpN = w >> 2;        // 0..1
    const int row0 = blockIdx.y * 128;
    const int col0 = blockIdx.x * 128;

    float acc[2][8][4];
#pragma unroll
    for (int mf = 0; mf < 2; mf++)
#pragma unroll
        for (int nf = 0; nf < 8; nf++)
#pragma unroll
            for (int i = 0; i < 4; i++) acc[mf][nf][i] = 0.f;

    for (int k0 = 0; k0 < K_GEMM; k0 += 32) {
        // stage A and W tiles (128x32 each), converting to tf32
#pragma unroll
        for (int i = 0; i < 4; i++) {
            const int slot = tid + i * 256;        // 0..1023
            const int r  = slot >> 3;
            const int kq = (slot & 7) * 4;
            float4 av = *(const float4*)(A + (size_t)(row0 + r) * K_GEMM + k0 + kq);
            float4 wv = *(const float4*)(W + (size_t)(col0 + r) * K_GEMM + k0 + kq);
            uint4 at = make_uint4(f2tf(av.x), f2tf(av.y), f2tf(av.z), f2tf(av.w));
            uint4 wt = make_uint4(f2tf(wv.x), f2tf(wv.y), f2tf(wv.z), f2tf(wv.w));
            *(uint4*)&As[r * ASTR + kq] = at;
            *(uint4*)&Ws[r * ASTR + kq] = wt;
        }
        __syncthreads();

#pragma unroll
        for (int ks = 0; ks < 4; ks++) {
            const int kk = ks * 8;
            uint32_t a[2][4];
#pragma unroll
            for (int mf = 0; mf < 2; mf++) {
                const int mr = warpM * 32 + mf * 16;
                a[mf][0] = As[(mr + g) * ASTR + kk + c];
                a[mf][1] = As[(mr + g + 8) * ASTR + kk + c];
                a[mf][2] = As[(mr + g) * ASTR + kk + c + 4];
                a[mf][3] = As[(mr + g + 8) * ASTR + kk + c + 4];
            }
#pragma unroll
            for (int nf = 0; nf < 8; nf++) {
                const int nr = warpN * 64 + nf * 8 + g;
                const uint32_t b0 = Ws[nr * ASTR + kk + c];
                const uint32_t b1 = Ws[nr * ASTR + kk + c + 4];
#pragma unroll
                for (int mf = 0; mf < 2; mf++) {
                    mma_tf32(acc[mf][nf][0], acc[mf][nf][1],
                             acc[mf][nf][2], acc[mf][nf][3],
                             a[mf][0], a[mf][1], a[mf][2], a[mf][3], b0, b1);
                }
            }
        }
        __syncthreads();
    }

    // epilogue: bias + scatter into Q/K/V ([b][h][s][64])
#pragma unroll
    for (int nf = 0; nf < 8; nf++) {
#pragma unroll
        for (int p = 0; p < 2; p++) {
            const int n = col0 + warpN * 64 + nf * 8 + c * 2 + p;
            const int h = n / 192;
            const int r = n - h * 192;
            const int which = r >> 6;
            const int d = r & 63;
            float* dst = (which == 0) ? g_Q : ((which == 1) ? g_K : g_V);
            const float bv = bias[n];
#pragma unroll
            for (int mf = 0; mf < 2; mf++) {
                const int m_lo = row0 + warpM * 32 + mf * 16 + g;
                int bb = m_lo >> 11, ss = m_lo & 2047;
                dst[((size_t)(bb * NHEADS + h) * SEQ + ss) * HDIM + d] = acc[mf][nf][p] + bv;
                const int m_hi = m_lo + 8;
                bb = m_hi >> 11; ss = m_hi & 2047;
                dst[((size_t)(bb * NHEADS + h) * SEQ + ss) * HDIM + d] = acc[mf][nf][2 + p] + bv;
            }
        }
    }
}

// ---------------------------------------------------------------------------
// Kernel 2: flash attention, tf32 tensor cores.
// Block: 128 q-rows, 8 warps x 16 rows. Q fragments resident in registers.
// KV tiles of 128 keys in smem. Online softmax on MMA accumulators.
// P bounced through a per-warp smem slice (C-layout -> A-layout).
// ---------------------------------------------------------------------------
#define KSTR 68    // (4g+c)%32 distinct
#define VSTR 72    // (8c+g)%32 distinct
#define PSTR 132   // (4g+c)%32 distinct

#define ATTN_SMEM ((128 * KSTR + 128 * VSTR + 8 * 16 * PSTR) * 4)

__global__ __launch_bounds__(256) void attn_kernel(float* __restrict__ out)
{
    extern __shared__ uint32_t sm[];
    uint32_t* Ks = sm;
    uint32_t* Vs = sm + 128 * KSTR;
    uint32_t* Ps = sm + 128 * KSTR + 128 * VSTR;

    const int tid  = threadIdx.x;
    const int w    = tid >> 5;
    const int lane = tid & 31;
    const int g    = lane >> 2;
    const int c    = lane & 3;
    const int bh   = blockIdx.y;
    const int q0   = blockIdx.x * 128;

    const float* Qg = g_Q + ((size_t)bh * SEQ + q0 + w * 16) * HDIM;

    // Q fragments: 8 k-steps x 4 regs, reused for all KV tiles
    uint32_t qa[8][4];
#pragma unroll
    for (int ks = 0; ks < 8; ks++) {
        qa[ks][0] = f2tf(Qg[(size_t)g * HDIM + ks * 8 + c]);
        qa[ks][1] = f2tf(Qg[(size_t)(g + 8) * HDIM + ks * 8 + c]);
        qa[ks][2] = f2tf(Qg[(size_t)g * HDIM + ks * 8 + c + 4]);
        qa[ks][3] = f2tf(Qg[(size_t)(g + 8) * HDIM + ks * 8 + c + 4]);
    }

    float o[8][4];
#pragma unroll
    for (int nf = 0; nf < 8; nf++)
#pragma unroll
        for (int i = 0; i < 4; i++) o[nf][i] = 0.f;

    float m0 = -1e30f, m1 = -1e30f, l0 = 0.f, l1 = 0.f;

    const float* Kg = g_K + (size_t)bh * SEQ * HDIM;
    const float* Vg = g_V + (size_t)bh * SEQ * HDIM;
    uint32_t* Pw = Ps + w * 16 * PSTR;

    for (int kt = 0; kt < SEQ; kt += 128) {
        __syncthreads();
        // stage K and V tiles (128x64 each)
#pragma unroll
        for (int i = 0; i < 8; i++) {
            const int slot = tid + i * 256;        // 0..2047
            const int r  = slot >> 4;
            const int q4 = (slot & 15) * 4;
            float4 kv = *(const float4*)(Kg + (size_t)(kt + r) * HDIM + q4);
            float4 vv = *(const float4*)(Vg + (size_t)(kt + r) * HDIM + q4);
            uint4 kq = make_uint4(f2tf(kv.x), f2tf(kv.y), f2tf(kv.z), f2tf(kv.w));
            uint4 vq = make_uint4(f2tf(vv.x), f2tf(vv.y), f2tf(vv.z), f2tf(vv.w));
            *(uint4*)&Ks[r * KSTR + q4] = kq;
            *(uint4*)&Vs[r * VSTR + q4] = vq;
        }
        __syncthreads();

        // S = Q @ K^T  (16 x 128 per warp)
        float s[16][4];
#pragma unroll
        for (int nf = 0; nf < 16; nf++)
#pragma unroll
            for (int i = 0; i < 4; i++) s[nf][i] = 0.f;

#pragma unroll
        for (int ks = 0; ks < 8; ks++) {
            const int kk = ks * 8;
#pragma unroll
            for (int nf = 0; nf < 16; nf++) {
                const uint32_t b0 = Ks[(nf * 8 + g) * KSTR + kk + c];
                const uint32_t b1 = Ks[(nf * 8 + g) * KSTR + kk + c + 4];
                mma_tf32(s[nf][0], s[nf][1], s[nf][2], s[nf][3],
                         qa[ks][0], qa[ks][1], qa[ks][2], qa[ks][3], b0, b1);
            }
        }

        // online softmax (rows g and g+8 of this warp's 16-row tile)
        float rmax0 = -1e30f, rmax1 = -1e30f;
#pragma unroll
        for (int nf = 0; nf < 16; nf++) {
            s[nf][0] *= 0.125f; s[nf][1] *= 0.125f;
            s[nf][2] *= 0.125f; s[nf][3] *= 0.125f;
            rmax0 = fmaxf(rmax0, fmaxf(s[nf][0], s[nf][1]));
            rmax1 = fmaxf(rmax1, fmaxf(s[nf][2], s[nf][3]));
        }
        rmax0 = fmaxf(rmax0, __shfl_xor_sync(0xffffffff, rmax0, 1));
        rmax0 = fmaxf(rmax0, __shfl_xor_sync(0xffffffff, rmax0, 2));
        rmax1 = fmaxf(rmax1, __shfl_xor_sync(0xffffffff, rmax1, 1));
        rmax1 = fmaxf(rmax1, __shfl_xor_sync(0xffffffff, rmax1, 2));

        const float mn0 = fmaxf(m0, rmax0);
        const float mn1 = fmaxf(m1, rmax1);
        const float corr0 = __expf(m0 - mn0);
        const float corr1 = __expf(m1 - mn1);

        float rs0 = 0.f, rs1 = 0.f;
#pragma unroll
        for (int nf = 0; nf < 16; nf++) {
            s[nf][0] = __expf(s[nf][0] - mn0); rs0 += s[nf][0];
            s[nf][1] = __expf(s[nf][1] - mn0); rs0 += s[nf][1];
            s[nf][2] = __expf(s[nf][2] - mn1); rs1 += s[nf][2];
            s[nf][3] = __expf(s[nf][3] - mn1); rs1 += s[nf][3];
        }
        rs0 += __shfl_xor_sync(0xffffffff, rs0, 1);
        rs0 += __shfl_xor_sync(0xffffffff, rs0, 2);
        rs1 += __shfl_xor_sync(0xffffffff, rs1, 1);
        rs1 += __shfl_xor_sync(0xffffffff, rs1, 2);

        l0 = l0 * corr0 + rs0;
        l1 = l1 * corr1 + rs1;
        m0 = mn0; m1 = mn1;

#pragma unroll
        for (int nf = 0; nf < 8; nf++) {
            o[nf][0] *= corr0; o[nf][1] *= corr0;
            o[nf][2] *= corr1; o[nf][3] *= corr1;
        }

        // write P (C-layout -> smem, tf32)
#pragma unroll
        for (int nf = 0; nf < 16; nf++) {
            uint2 lo = make_uint2(f2tf(s[nf][0]), f2tf(s[nf][1]));
            uint2 hi = make_uint2(f2tf(s[nf][2]), f2tf(s[nf][3]));
            *(uint2*)&Pw[g * PSTR + nf * 8 + c * 2] = lo;
            *(uint2*)&Pw[(g + 8) * PSTR + nf * 8 + c * 2] = hi;
        }
        __syncwarp();

        // O += P @ V  (16 x 64 per warp, k = 128)
#pragma unroll
        for (int ks = 0; ks < 16; ks++) {
            const int kk = ks * 8;
            const uint32_t a0 = Pw[g * PSTR + kk + c];
            const uint32_t a1 = Pw[(g + 8) * PSTR + kk + c];
            const uint32_t a2 = Pw[g * PSTR + kk + c + 4];
            const uint32_t a3 = Pw[(g + 8) * PSTR + kk + c + 4];
#pragma unroll
            for (int nf = 0; nf < 8; nf++) {
                const uint32_t b0 = Vs[(kk + c) * VSTR + nf * 8 + g];
                const uint32_t b1 = Vs[(kk + c + 4) * VSTR + nf * 8 + g];
                mma_tf32(o[nf][0], o[nf][1], o[nf][2], o[nf][3],
                         a0, a1, a2, a3, b0, b1);
            }
        }
        __syncwarp();
    }

    // epilogue: normalize and store (out is [b][h][s][64] flat)
    const float inv0 = 1.f / l0;
    const float inv1 = 1.f / l1;
    float* orow = out + ((size_t)bh * SEQ + q0 + w * 16) * HDIM;
#pragma unroll
    for (int nf = 0; nf < 8; nf++) {
        const int col = nf * 8 + c * 2;
        float2 lo = make_float2(o[nf][0] * inv0, o[nf][1] * inv0);
        float2 hi = make_float2(o[nf][2] * inv1, o[nf][3] * inv1);
        *(float2*)&orow[(size_t)g * HDIM + col] = lo;
        *(float2*)&orow[(size_t)(g + 8) * HDIM + col] = hi;
    }
}

// ---------------------------------------------------------------------------
extern "C" void kernel_launch(void* const* d_in, const int* in_sizes, int n_in,
                              void* d_out, int out_size)
{
    const float* x = (const float*)d_in[0];   // [2, 2048, 1024]
    const float* w = (const float*)d_in[1];   // [3072, 1024]
    const float* b = (const float*)d_in[2];   // [3072]
    float* out = (float*)d_out;               // [2, 2048, 1024] (head-interleaved)

    cudaFuncSetAttribute(attn_kernel,
                         cudaFuncAttributeMaxDynamicSharedMemorySize, ATTN_SMEM);

    dim3 ggrid(NOUT / 128, M_GEMM / 128);     // (24, 32)
    qkv_gemm_kernel<<<ggrid, 256>>>(x, w, b);

    dim3 agrid(SEQ / 128, BATCH * NHEADS);    // (16, 32)
    attn_kernel<<<agrid, 256, ATTN_SMEM>>>(out);
}